// round 5
// baseline (speedup 1.0000x reference)
#include <cuda_runtime.h>
#include <cuda_bf16.h>
#include <cuda_fp16.h>
#include <cstdint>

// Problem constants
#define Dk   512
#define Ek   4
#define Vk   32000
#define Lk   1024
#define M2k  (Lk * Ek)     // 4096 rows for the big GEMM
#define N1k  (Ek * Dk)     // 2048 latent width

// ---------------------------------------------------------------------------
// Device scratch (allocation-free: static __device__ arrays)
// ---------------------------------------------------------------------------
__device__ __nv_bfloat16 g_Hbf[Lk * Dk];                 // hidden bf16 [1024][512]
__device__ __nv_bfloat16 g_Wlat[Dk * N1k];               // W_latent bf16 [512][2048]
__device__ __half        g_WdecH[Dk * Vk];               // W_dec fp16 [512][32000]
__device__ __half        g_latent[M2k * Dk];             // tanh latent fp16 [4096][512]
__device__ __half        g_logits[(size_t)M2k * Vk];     // 262 MB logits scratch (fp16)
__device__ float         g_logcoef[M2k];                 // log softmax of priors
__device__ float         g_sumexp[M2k];                  // per-(l,e) sum of exp(logit)
__device__ float         g_w[M2k];                       // exp(logcoef)/sumexp

__device__ __forceinline__ uint32_t smem_u32(const void* p) {
    return (uint32_t)__cvta_generic_to_shared(p);
}
__device__ __forceinline__ void cpasync16(uint32_t sp, const void* gp) {
    asm volatile("cp.async.cg.shared.global [%0], [%1], 16;\n" :: "r"(sp), "l"(gp));
}

// ---------------------------------------------------------------------------
// fp32 -> bf16 / fp16 conversions
// ---------------------------------------------------------------------------
__global__ void conv_kernel(const float* __restrict__ H,
                            const float* __restrict__ Wl,
                            const float* __restrict__ Wd) {
    int stride = gridDim.x * blockDim.x;
    int tid = blockIdx.x * blockDim.x + threadIdx.x;
    for (int j = tid; j < Lk * Dk; j += stride)  g_Hbf[j]  = __float2bfloat16(H[j]);
    for (int j = tid; j < Dk * N1k; j += stride) g_Wlat[j] = __float2bfloat16(Wl[j]);
    for (int j = tid; j < Dk * Vk; j += stride)  g_WdecH[j] = __float2half(Wd[j]);
}

// ---------------------------------------------------------------------------
// Prior: one warp per token, 4 dots + log_softmax. Also zeroes g_sumexp.
// ---------------------------------------------------------------------------
__global__ void prior_kernel(const float* __restrict__ H,
                             const float* __restrict__ Wp,
                             const float* __restrict__ bp) {
    int gtid = blockIdx.x * blockDim.x + threadIdx.x;
    if (gtid < M2k) g_sumexp[gtid] = 0.f;
    int w = gtid >> 5, lane = gtid & 31;
    if (w >= Lk) return;
    float a0 = 0.f, a1 = 0.f, a2 = 0.f, a3 = 0.f;
    const float* h = H + w * Dk;
    for (int d = lane; d < Dk; d += 32) {
        float hv = h[d];
        const float* wr = Wp + d * Ek;
        a0 += hv * wr[0]; a1 += hv * wr[1]; a2 += hv * wr[2]; a3 += hv * wr[3];
    }
#pragma unroll
    for (int o = 16; o; o >>= 1) {
        a0 += __shfl_xor_sync(0xffffffffu, a0, o);
        a1 += __shfl_xor_sync(0xffffffffu, a1, o);
        a2 += __shfl_xor_sync(0xffffffffu, a2, o);
        a3 += __shfl_xor_sync(0xffffffffu, a3, o);
    }
    if (lane == 0) {
        float x0 = a0 + bp[0], x1 = a1 + bp[1], x2 = a2 + bp[2], x3 = a3 + bp[3];
        float mx = fmaxf(fmaxf(x0, x1), fmaxf(x2, x3));
        float s = __expf(x0 - mx) + __expf(x1 - mx) + __expf(x2 - mx) + __expf(x3 - mx);
        float lse = mx + __logf(s);
        g_logcoef[w * Ek + 0] = x0 - lse;  g_logcoef[w * Ek + 1] = x1 - lse;
        g_logcoef[w * Ek + 2] = x2 - lse;  g_logcoef[w * Ek + 3] = x3 - lse;
    }
}

// ---------------------------------------------------------------------------
// GEMM1 (latent): bf16 in, fp32 accum, 128x128x32 tiles; out -> fp16 latent
// ---------------------------------------------------------------------------
#define BM1 128
#define BN1 128
#define BK1 32
#define KT1 (Dk / BK1)
#define PADA 40
#define PADB 136

__global__ __launch_bounds__(256, 2) void gemm1_kernel(const float* __restrict__ bias) {
    const int N = N1k;
    const __nv_bfloat16* __restrict__ A  = g_Hbf;
    const __nv_bfloat16* __restrict__ Bm = g_Wlat;

    __shared__ __align__(16) __nv_bfloat16 As[2][BM1][PADA];
    __shared__ __align__(16) __nv_bfloat16 Bs[2][BK1][PADB];

    const int tid = threadIdx.x, lane = tid & 31, wid = tid >> 5;
    const int warp_m = wid >> 2, warp_n = wid & 3;
    const int mBase = blockIdx.y * BM1, nBase = blockIdx.x * BN1;

    float c[4][4][4];
#pragma unroll
    for (int i = 0; i < 4; i++)
#pragma unroll
        for (int j = 0; j < 4; j++)
#pragma unroll
            for (int r = 0; r < 4; r++) c[i][j][r] = 0.f;

    auto issue = [&](int kt, int buf) {
#pragma unroll
        for (int s = 0; s < 2; s++) {
            int chunk = tid + s * 256;
            int arow = chunk >> 2, ac4 = chunk & 3;
            cpasync16(smem_u32(&As[buf][arow][ac4 * 8]),
                      A + (size_t)(mBase + arow) * Dk + kt * BK1 + ac4 * 8);
        }
#pragma unroll
        for (int s = 0; s < 2; s++) {
            int chunk = tid + s * 256;
            int brow = chunk >> 4, bc4 = chunk & 15;
            cpasync16(smem_u32(&Bs[buf][brow][bc4 * 8]),
                      Bm + (size_t)(kt * BK1 + brow) * N + nBase + bc4 * 8);
        }
    };

    auto compute = [&](int buf) {
#pragma unroll
        for (int ks = 0; ks < 2; ks++) {
            const int k0 = ks * 16;
            uint32_t a[4][4], b[4][2];
#pragma unroll
            for (int i = 0; i < 4; i++) {
                int row = warp_m * 64 + i * 16 + (lane & 7) + ((lane >> 3) & 1) * 8;
                int col = k0 + (lane >> 4) * 8;
                uint32_t ad = smem_u32(&As[buf][row][col]);
                asm volatile("ldmatrix.sync.aligned.m8n8.x4.shared.b16 {%0,%1,%2,%3}, [%4];"
                             : "=r"(a[i][0]), "=r"(a[i][1]), "=r"(a[i][2]), "=r"(a[i][3])
                             : "r"(ad));
            }
#pragma unroll
            for (int jj = 0; jj < 2; jj++) {
                int krow = k0 + (lane & 7) + ((lane >> 3) & 1) * 8;
                int ncol = warp_n * 32 + jj * 16 + (lane >> 4) * 8;
                uint32_t ad = smem_u32(&Bs[buf][krow][ncol]);
                asm volatile("ldmatrix.sync.aligned.m8n8.x4.trans.shared.b16 {%0,%1,%2,%3}, [%4];"
                             : "=r"(b[jj * 2][0]), "=r"(b[jj * 2][1]),
                               "=r"(b[jj * 2 + 1][0]), "=r"(b[jj * 2 + 1][1])
                             : "r"(ad));
            }
#pragma unroll
            for (int i = 0; i < 4; i++)
#pragma unroll
                for (int j = 0; j < 4; j++) {
                    asm volatile(
                        "mma.sync.aligned.m16n8k16.row.col.f32.bf16.bf16.f32 "
                        "{%0,%1,%2,%3}, {%4,%5,%6,%7}, {%8,%9}, {%0,%1,%2,%3};"
                        : "+f"(c[i][j][0]), "+f"(c[i][j][1]), "+f"(c[i][j][2]), "+f"(c[i][j][3])
                        : "r"(a[i][0]), "r"(a[i][1]), "r"(a[i][2]), "r"(a[i][3]),
                          "r"(b[j][0]), "r"(b[j][1]));
                }
        }
    };

    issue(0, 0);
    asm volatile("cp.async.commit_group;\n");
    issue(1, 1);
    asm volatile("cp.async.commit_group;\n");

    for (int kt = 0; kt < KT1; kt++) {
        if (kt < KT1 - 1) { asm volatile("cp.async.wait_group 1;\n"); }
        else              { asm volatile("cp.async.wait_group 0;\n"); }
        __syncthreads();
        compute(kt & 1);
        if (kt + 2 < KT1) {
            __syncthreads();
            issue(kt + 2, kt & 1);
            asm volatile("cp.async.commit_group;\n");
        }
    }

#pragma unroll
    for (int j = 0; j < 4; j++) {
        int col = nBase + warp_n * 32 + j * 8 + (lane & 3) * 2;
        float b0 = bias[col], b1 = bias[col + 1];
#pragma unroll
        for (int i = 0; i < 4; i++) {
            int row = mBase + warp_m * 64 + i * 16 + (lane >> 2);
            __half2 p0 = __floats2half2_rn(tanhf(c[i][j][0] + b0), tanhf(c[i][j][1] + b1));
            __half2 p1 = __floats2half2_rn(tanhf(c[i][j][2] + b0), tanhf(c[i][j][3] + b1));
            *reinterpret_cast<__half2*>(&g_latent[(size_t)row * N + col]) = p0;
            *reinterpret_cast<__half2*>(&g_latent[(size_t)(row + 8) * N + col]) = p1;
        }
    }
}

// ---------------------------------------------------------------------------
// GEMM2 (decoder): fp16 in, FP16 ACCUM (2x legacy tensor rate).
// 128x128 CTA tile, 8 warps, warp tile 64x32, 4-stage cp.async pipeline,
// one __syncthreads per K-chunk, 2 CTAs/SM.
// ---------------------------------------------------------------------------
#define G2_BM 128
#define G2_BN 128
#define G2_BK 32
#define G2_KT (Dk / G2_BK)              // 16
#define G2_AROWB 80                     // (32+8) fp16
#define G2_BROWB 272                    // (128+8) fp16
#define G2_ABYTES (G2_BM * G2_AROWB)    // 10240
#define G2_BBYTES (G2_BK * G2_BROWB)    // 8704
#define G2_STG    (G2_ABYTES + G2_BBYTES)   // 18944
#define G2_NSTG   4
#define G2_DSMEM  (G2_NSTG * G2_STG)        // 75776

__global__ __launch_bounds__(256, 2) void gemm2_kernel(const float* __restrict__ bias) {
    extern __shared__ char dsm[];
    __shared__ float srow[G2_BM];

    const int tid  = threadIdx.x;
    const int lane = tid & 31;
    const int wid  = tid >> 5;
    const int warp_m = wid >> 2;       // 0..1
    const int warp_n = wid & 3;        // 0..3
    const int mBase = blockIdx.y * G2_BM;
    const int nBase = blockIdx.x * G2_BN;

    const uint32_t s0 = smem_u32(dsm);
    const __half* __restrict__ A  = g_latent;
    const __half* __restrict__ Bm = g_WdecH;

    // fp16 accumulators: c[i][j][0] = rows (lane>>2), c[i][j][1] = rows+8 (half2 each)
    uint32_t c[4][4][2];
#pragma unroll
    for (int i = 0; i < 4; i++)
#pragma unroll
        for (int j = 0; j < 4; j++) { c[i][j][0] = 0u; c[i][j][1] = 0u; }

    auto issue = [&](int kt) {
        const uint32_t aB = s0 + (uint32_t)(kt & (G2_NSTG - 1)) * G2_STG;
        const uint32_t bB = aB + G2_ABYTES;
#pragma unroll
        for (int s = 0; s < 2; s++) {              // A: 512 x16B chunks
            int ch = tid + s * 256;
            int row = ch >> 2, cc = ch & 3;
            cpasync16(aB + (uint32_t)(row * G2_AROWB + cc * 16),
                      A + (size_t)(mBase + row) * Dk + kt * G2_BK + cc * 8);
        }
#pragma unroll
        for (int s = 0; s < 2; s++) {              // B: 512 x16B chunks
            int ch = tid + s * 256;
            int row = ch >> 4, cc = ch & 15;
            cpasync16(bB + (uint32_t)(row * G2_BROWB + cc * 16),
                      Bm + (size_t)(kt * G2_BK + row) * Vk + nBase + cc * 8);
        }
        asm volatile("cp.async.commit_group;\n");
    };

    auto compute = [&](int kt) {
        const uint32_t aB = s0 + (uint32_t)(kt & (G2_NSTG - 1)) * G2_STG;
        const uint32_t bB = aB + G2_ABYTES;
#pragma unroll
        for (int ks = 0; ks < 2; ks++) {
            const int k0 = ks * 16;
            uint32_t a[4][4], b[4][2];
#pragma unroll
            for (int i = 0; i < 4; i++) {
                int row = warp_m * 64 + i * 16 + (lane & 7) + ((lane >> 3) & 1) * 8;
                int col = k0 + (lane >> 4) * 8;
                uint32_t ad = aB + (uint32_t)(row * G2_AROWB + col * 2);
                asm volatile("ldmatrix.sync.aligned.m8n8.x4.shared.b16 {%0,%1,%2,%3}, [%4];"
                             : "=r"(a[i][0]), "=r"(a[i][1]), "=r"(a[i][2]), "=r"(a[i][3])
                             : "r"(ad));
            }
#pragma unroll
            for (int jj = 0; jj < 2; jj++) {
                int krow = k0 + (lane & 7) + ((lane >> 3) & 1) * 8;
                int ncol = warp_n * 32 + jj * 16 + (lane >> 4) * 8;
                uint32_t ad = bB + (uint32_t)(krow * G2_BROWB + ncol * 2);
                asm volatile("ldmatrix.sync.aligned.m8n8.x4.trans.shared.b16 {%0,%1,%2,%3}, [%4];"
                             : "=r"(b[jj * 2][0]), "=r"(b[jj * 2][1]),
                               "=r"(b[jj * 2 + 1][0]), "=r"(b[jj * 2 + 1][1])
                             : "r"(ad));
            }
#pragma unroll
            for (int i = 0; i < 4; i++)
#pragma unroll
                for (int j = 0; j < 4; j++) {
                    asm volatile(
                        "mma.sync.aligned.m16n8k16.row.col.f16.f16.f16.f16 "
                        "{%0,%1}, {%2,%3,%4,%5}, {%6,%7}, {%0,%1};"
                        : "+r"(c[i][j][0]), "+r"(c[i][j][1])
                        : "r"(a[i][0]), "r"(a[i][1]), "r"(a[i][2]), "r"(a[i][3]),
                          "r"(b[j][0]), "r"(b[j][1]));
                }
        }
    };

    issue(0);
    issue(1);
    issue(2);

    for (int kt = 0; kt < G2_KT; kt++) {
        if (kt < G2_KT - 2)      { asm volatile("cp.async.wait_group 2;\n"); }
        else if (kt < G2_KT - 1) { asm volatile("cp.async.wait_group 1;\n"); }
        else                     { asm volatile("cp.async.wait_group 0;\n"); }
        __syncthreads();
        if (kt + 3 < G2_KT) issue(kt + 3);
        compute(kt);
    }

    // -------- epilogue --------
    if (tid < G2_BM) srow[tid] = 0.f;
    __syncthreads();

    float rs[4][2];
#pragma unroll
    for (int i = 0; i < 4; i++) { rs[i][0] = 0.f; rs[i][1] = 0.f; }

#pragma unroll
    for (int j = 0; j < 4; j++) {
        int col = nBase + warp_n * 32 + j * 8 + (lane & 3) * 2;
        float b0 = bias[col], b1 = bias[col + 1];
#pragma unroll
        for (int i = 0; i < 4; i++) {
            int row = mBase + warp_m * 64 + i * 16 + (lane >> 2);
            float2 f0 = __half22float2(*reinterpret_cast<__half2*>(&c[i][j][0]));
            float2 f1 = __half22float2(*reinterpret_cast<__half2*>(&c[i][j][1]));
            float v00 = f0.x + b0, v01 = f0.y + b1;
            float v10 = f1.x + b0, v11 = f1.y + b1;
            *reinterpret_cast<__half2*>(&g_logits[(size_t)row * Vk + col]) =
                __floats2half2_rn(v00, v01);
            *reinterpret_cast<__half2*>(&g_logits[(size_t)(row + 8) * Vk + col]) =
                __floats2half2_rn(v10, v11);
            rs[i][0] += __expf(v00) + __expf(v01);
            rs[i][1] += __expf(v10) + __expf(v11);
        }
    }
#pragma unroll
    for (int i = 0; i < 4; i++)
#pragma unroll
        for (int h = 0; h < 2; h++) {
            float v = rs[i][h];
            v += __shfl_xor_sync(0xffffffffu, v, 1);
            v += __shfl_xor_sync(0xffffffffu, v, 2);
            if ((lane & 3) == 0)
                atomicAdd(&srow[warp_m * 64 + i * 16 + (lane >> 2) + h * 8], v);
        }
    __syncthreads();
    if (tid < G2_BM) atomicAdd(&g_sumexp[mBase + tid], srow[tid]);
}

// ---------------------------------------------------------------------------
// w[l,e] = exp(log_coef) / sumexp
// ---------------------------------------------------------------------------
__global__ void prep_w_kernel() {
    int m = blockIdx.x * blockDim.x + threadIdx.x;
    if (m < M2k) g_w[m] = __expf(g_logcoef[m]) / g_sumexp[m];
}

// ---------------------------------------------------------------------------
// out[l,v] = log( sum_e w[l,e] * exp(logit[l,e,v]) )
// ---------------------------------------------------------------------------
__global__ void combine_kernel(float* __restrict__ out) {
    int v = (blockIdx.x * blockDim.x + threadIdx.x) * 2;
    int l = blockIdx.y;
    const __half* lp = g_logits + (size_t)l * Ek * Vk + v;
    const float*  wp = g_w + l * Ek;
    float s0 = 0.f, s1 = 0.f;
#pragma unroll
    for (int e = 0; e < Ek; e++) {
        __half2 h2 = *reinterpret_cast<const __half2*>(lp + (size_t)e * Vk);
        float2 f2 = __half22float2(h2);
        float we = wp[e];
        s0 += we * __expf(f2.x);
        s1 += we * __expf(f2.y);
    }
    float2* o2 = reinterpret_cast<float2*>(out + (size_t)l * Vk + v);
    *o2 = make_float2(__logf(s0), __logf(s1));
}

// ---------------------------------------------------------------------------
// Entry point (graph-capturable: kernel launches only)
// ---------------------------------------------------------------------------
extern "C" void kernel_launch(void* const* d_in, const int* in_sizes, int n_in,
                              void* d_out, int out_size) {
    const float* H  = (const float*)d_in[0];
    const float* Wp = (const float*)d_in[1];
    const float* bp = (const float*)d_in[2];
    const float* Wl = (const float*)d_in[3];
    const float* bl = (const float*)d_in[4];
    const float* Wd = (const float*)d_in[5];
    const float* bd = (const float*)d_in[6];
    float* out = (float*)d_out;

    static bool attr_set = false;
    if (!attr_set) {
        cudaFuncSetAttribute(gemm2_kernel,
                             cudaFuncAttributeMaxDynamicSharedMemorySize, G2_DSMEM);
        attr_set = true;
    }

    conv_kernel<<<2048, 256>>>(H, Wl, Wd);
    prior_kernel<<<128, 256>>>(H, Wp, bp);
    gemm1_kernel<<<dim3(N1k / BN1, Lk / BM1), 256>>>(bl);                 // (16, 8)
    gemm2_kernel<<<dim3(Vk / G2_BN, M2k / G2_BM), 256, G2_DSMEM>>>(bd);   // (250, 32)
    prep_w_kernel<<<(M2k + 255) / 256, 256>>>();
    combine_kernel<<<dim3(125, Lk), 128>>>(out);                          // (125, 1024)
}

// round 6
// speedup vs baseline: 1.1454x; 1.1454x over previous
#include <cuda_runtime.h>
#include <cuda_bf16.h>
#include <cuda_fp16.h>
#include <cstdint>

// Problem constants
#define Dk   512
#define Ek   4
#define Vk   32000
#define Lk   1024
#define M2k  (Lk * Ek)     // 4096 rows for the big GEMM
#define N1k  (Ek * Dk)     // 2048 latent width

// ---------------------------------------------------------------------------
// Device scratch (allocation-free: static __device__ arrays)
// ---------------------------------------------------------------------------
__device__ __nv_bfloat16 g_Hbf[Lk * Dk];                 // hidden bf16 [1024][512]
__device__ __nv_bfloat16 g_Wlat[Dk * N1k];               // W_latent bf16 [512][2048]
__device__ __half        g_WdecH[Dk * Vk];               // W_dec fp16 [512][32000]
__device__ __half        g_latent[M2k * Dk];             // tanh latent fp16 [4096][512]
__device__ __half        g_logits[(size_t)M2k * Vk];     // 262 MB logits scratch (fp16)
__device__ float         g_logcoef[M2k];                 // log softmax of priors
__device__ float         g_sumexp[M2k];                  // per-(l,e) sum of exp(logit)
__device__ float         g_w[M2k];                       // exp(logcoef)/sumexp

__device__ __forceinline__ uint32_t smem_u32(const void* p) {
    return (uint32_t)__cvta_generic_to_shared(p);
}
__device__ __forceinline__ void cpasync16(uint32_t sp, const void* gp) {
    asm volatile("cp.async.cg.shared.global [%0], [%1], 16;\n" :: "r"(sp), "l"(gp));
}

// ---------------------------------------------------------------------------
// fp32 -> bf16 / fp16 conversions
// ---------------------------------------------------------------------------
__global__ void conv_kernel(const float* __restrict__ H,
                            const float* __restrict__ Wl,
                            const float* __restrict__ Wd) {
    int stride = gridDim.x * blockDim.x;
    int tid = blockIdx.x * blockDim.x + threadIdx.x;
    for (int j = tid; j < Lk * Dk; j += stride)  g_Hbf[j]  = __float2bfloat16(H[j]);
    for (int j = tid; j < Dk * N1k; j += stride) g_Wlat[j] = __float2bfloat16(Wl[j]);
    for (int j = tid; j < Dk * Vk; j += stride)  g_WdecH[j] = __float2half(Wd[j]);
}

// ---------------------------------------------------------------------------
// Prior: one warp per token, 4 dots + log_softmax. Also zeroes g_sumexp.
// ---------------------------------------------------------------------------
__global__ void prior_kernel(const float* __restrict__ H,
                             const float* __restrict__ Wp,
                             const float* __restrict__ bp) {
    int gtid = blockIdx.x * blockDim.x + threadIdx.x;
    if (gtid < M2k) g_sumexp[gtid] = 0.f;
    int w = gtid >> 5, lane = gtid & 31;
    if (w >= Lk) return;
    float a0 = 0.f, a1 = 0.f, a2 = 0.f, a3 = 0.f;
    const float* h = H + w * Dk;
    for (int d = lane; d < Dk; d += 32) {
        float hv = h[d];
        const float* wr = Wp + d * Ek;
        a0 += hv * wr[0]; a1 += hv * wr[1]; a2 += hv * wr[2]; a3 += hv * wr[3];
    }
#pragma unroll
    for (int o = 16; o; o >>= 1) {
        a0 += __shfl_xor_sync(0xffffffffu, a0, o);
        a1 += __shfl_xor_sync(0xffffffffu, a1, o);
        a2 += __shfl_xor_sync(0xffffffffu, a2, o);
        a3 += __shfl_xor_sync(0xffffffffu, a3, o);
    }
    if (lane == 0) {
        float x0 = a0 + bp[0], x1 = a1 + bp[1], x2 = a2 + bp[2], x3 = a3 + bp[3];
        float mx = fmaxf(fmaxf(x0, x1), fmaxf(x2, x3));
        float s = __expf(x0 - mx) + __expf(x1 - mx) + __expf(x2 - mx) + __expf(x3 - mx);
        float lse = mx + __logf(s);
        g_logcoef[w * Ek + 0] = x0 - lse;  g_logcoef[w * Ek + 1] = x1 - lse;
        g_logcoef[w * Ek + 2] = x2 - lse;  g_logcoef[w * Ek + 3] = x3 - lse;
    }
}

// ---------------------------------------------------------------------------
// GEMM1 (latent): bf16 in, fp32 accum, 128x128x32 tiles; out -> fp16 latent
// ---------------------------------------------------------------------------
#define BM1 128
#define BN1 128
#define BK1 32
#define KT1 (Dk / BK1)
#define PADA 40
#define PADB 136

__global__ __launch_bounds__(256, 2) void gemm1_kernel(const float* __restrict__ bias) {
    const int N = N1k;
    const __nv_bfloat16* __restrict__ A  = g_Hbf;
    const __nv_bfloat16* __restrict__ Bm = g_Wlat;

    __shared__ __align__(16) __nv_bfloat16 As[2][BM1][PADA];
    __shared__ __align__(16) __nv_bfloat16 Bs[2][BK1][PADB];

    const int tid = threadIdx.x, lane = tid & 31, wid = tid >> 5;
    const int warp_m = wid >> 2, warp_n = wid & 3;
    const int mBase = blockIdx.y * BM1, nBase = blockIdx.x * BN1;

    float c[4][4][4];
#pragma unroll
    for (int i = 0; i < 4; i++)
#pragma unroll
        for (int j = 0; j < 4; j++)
#pragma unroll
            for (int r = 0; r < 4; r++) c[i][j][r] = 0.f;

    auto issue = [&](int kt, int buf) {
#pragma unroll
        for (int s = 0; s < 2; s++) {
            int chunk = tid + s * 256;
            int arow = chunk >> 2, ac4 = chunk & 3;
            cpasync16(smem_u32(&As[buf][arow][ac4 * 8]),
                      A + (size_t)(mBase + arow) * Dk + kt * BK1 + ac4 * 8);
        }
#pragma unroll
        for (int s = 0; s < 2; s++) {
            int chunk = tid + s * 256;
            int brow = chunk >> 4, bc4 = chunk & 15;
            cpasync16(smem_u32(&Bs[buf][brow][bc4 * 8]),
                      Bm + (size_t)(kt * BK1 + brow) * N + nBase + bc4 * 8);
        }
    };

    auto compute = [&](int buf) {
#pragma unroll
        for (int ks = 0; ks < 2; ks++) {
            const int k0 = ks * 16;
            uint32_t a[4][4], b[4][2];
#pragma unroll
            for (int i = 0; i < 4; i++) {
                int row = warp_m * 64 + i * 16 + (lane & 7) + ((lane >> 3) & 1) * 8;
                int col = k0 + (lane >> 4) * 8;
                uint32_t ad = smem_u32(&As[buf][row][col]);
                asm volatile("ldmatrix.sync.aligned.m8n8.x4.shared.b16 {%0,%1,%2,%3}, [%4];"
                             : "=r"(a[i][0]), "=r"(a[i][1]), "=r"(a[i][2]), "=r"(a[i][3])
                             : "r"(ad));
            }
#pragma unroll
            for (int jj = 0; jj < 2; jj++) {
                int krow = k0 + (lane & 7) + ((lane >> 3) & 1) * 8;
                int ncol = warp_n * 32 + jj * 16 + (lane >> 4) * 8;
                uint32_t ad = smem_u32(&Bs[buf][krow][ncol]);
                asm volatile("ldmatrix.sync.aligned.m8n8.x4.trans.shared.b16 {%0,%1,%2,%3}, [%4];"
                             : "=r"(b[jj * 2][0]), "=r"(b[jj * 2][1]),
                               "=r"(b[jj * 2 + 1][0]), "=r"(b[jj * 2 + 1][1])
                             : "r"(ad));
            }
#pragma unroll
            for (int i = 0; i < 4; i++)
#pragma unroll
                for (int j = 0; j < 4; j++) {
                    asm volatile(
                        "mma.sync.aligned.m16n8k16.row.col.f32.bf16.bf16.f32 "
                        "{%0,%1,%2,%3}, {%4,%5,%6,%7}, {%8,%9}, {%0,%1,%2,%3};"
                        : "+f"(c[i][j][0]), "+f"(c[i][j][1]), "+f"(c[i][j][2]), "+f"(c[i][j][3])
                        : "r"(a[i][0]), "r"(a[i][1]), "r"(a[i][2]), "r"(a[i][3]),
                          "r"(b[j][0]), "r"(b[j][1]));
                }
        }
    };

    issue(0, 0);
    asm volatile("cp.async.commit_group;\n");
    issue(1, 1);
    asm volatile("cp.async.commit_group;\n");

    for (int kt = 0; kt < KT1; kt++) {
        if (kt < KT1 - 1) { asm volatile("cp.async.wait_group 1;\n"); }
        else              { asm volatile("cp.async.wait_group 0;\n"); }
        __syncthreads();
        compute(kt & 1);
        if (kt + 2 < KT1) {
            __syncthreads();
            issue(kt + 2, kt & 1);
            asm volatile("cp.async.commit_group;\n");
        }
    }

#pragma unroll
    for (int j = 0; j < 4; j++) {
        int col = nBase + warp_n * 32 + j * 8 + (lane & 3) * 2;
        float b0 = bias[col], b1 = bias[col + 1];
#pragma unroll
        for (int i = 0; i < 4; i++) {
            int row = mBase + warp_m * 64 + i * 16 + (lane >> 2);
            __half2 p0 = __floats2half2_rn(tanhf(c[i][j][0] + b0), tanhf(c[i][j][1] + b1));
            __half2 p1 = __floats2half2_rn(tanhf(c[i][j][2] + b0), tanhf(c[i][j][3] + b1));
            *reinterpret_cast<__half2*>(&g_latent[(size_t)row * N + col]) = p0;
            *reinterpret_cast<__half2*>(&g_latent[(size_t)(row + 8) * N + col]) = p1;
        }
    }
}

// ---------------------------------------------------------------------------
// GEMM2 (decoder): fp16 in, fp16 accum. CTA tile 128x256, 8 warps (2x4),
// WARP TILE 64x64 (halves smem reads per FLOP vs 64x32), 4-stage pipeline,
// one __syncthreads per K-chunk, 2 CTAs/SM.
// ---------------------------------------------------------------------------
#define G2_BM 128
#define G2_BN 256
#define G2_BK 32
#define G2_KT (Dk / G2_BK)              // 16
#define G2_AROWB 80                     // (32+8) fp16
#define G2_BROWB 528                    // (256+8) fp16
#define G2_ABYTES (G2_BM * G2_AROWB)    // 10240
#define G2_BBYTES (G2_BK * G2_BROWB)    // 16896
#define G2_STG    (G2_ABYTES + G2_BBYTES)   // 27136
#define G2_NSTG   4
#define G2_DSMEM  (G2_NSTG * G2_STG)        // 108544

__global__ __launch_bounds__(256, 2) void gemm2_kernel(const float* __restrict__ bias) {
    extern __shared__ char dsm[];
    __shared__ float srow[G2_BM];

    const int tid  = threadIdx.x;
    const int lane = tid & 31;
    const int wid  = tid >> 5;
    const int warp_m = wid >> 2;       // 0..1
    const int warp_n = wid & 3;        // 0..3
    const int mBase = blockIdx.y * G2_BM;
    const int nBase = blockIdx.x * G2_BN;

    const uint32_t s0 = smem_u32(dsm);
    const __half* __restrict__ A  = g_latent;
    const __half* __restrict__ Bm = g_WdecH;

    // fp16 accumulators: c[i][j][0] = row (lane>>2), [1] = row+8, cols j*8+(lane&3)*2
    uint32_t c[4][8][2];
#pragma unroll
    for (int i = 0; i < 4; i++)
#pragma unroll
        for (int j = 0; j < 8; j++) { c[i][j][0] = 0u; c[i][j][1] = 0u; }

    auto issue = [&](int kt) {
        const uint32_t aB = s0 + (uint32_t)(kt & (G2_NSTG - 1)) * G2_STG;
        const uint32_t bB = aB + G2_ABYTES;
#pragma unroll
        for (int s = 0; s < 2; s++) {              // A: 512 x16B chunks
            int ch = tid + s * 256;
            int row = ch >> 2, cc = ch & 3;
            cpasync16(aB + (uint32_t)(row * G2_AROWB + cc * 16),
                      A + (size_t)(mBase + row) * Dk + kt * G2_BK + cc * 8);
        }
#pragma unroll
        for (int s = 0; s < 4; s++) {              // B: 1024 x16B chunks
            int ch = tid + s * 256;
            int row = ch >> 5, cc = ch & 31;
            cpasync16(bB + (uint32_t)(row * G2_BROWB + cc * 16),
                      Bm + (size_t)(kt * G2_BK + row) * Vk + nBase + cc * 8);
        }
        asm volatile("cp.async.commit_group;\n");
    };

    auto compute = [&](int kt) {
        const uint32_t aB = s0 + (uint32_t)(kt & (G2_NSTG - 1)) * G2_STG;
        const uint32_t bB = aB + G2_ABYTES;
#pragma unroll
        for (int ks = 0; ks < 2; ks++) {
            const int k0 = ks * 16;
            uint32_t a[4][4], b[8][2];
#pragma unroll
            for (int i = 0; i < 4; i++) {
                int row = warp_m * 64 + i * 16 + (lane & 7) + ((lane >> 3) & 1) * 8;
                int col = k0 + (lane >> 4) * 8;
                uint32_t ad = aB + (uint32_t)(row * G2_AROWB + col * 2);
                asm volatile("ldmatrix.sync.aligned.m8n8.x4.shared.b16 {%0,%1,%2,%3}, [%4];"
                             : "=r"(a[i][0]), "=r"(a[i][1]), "=r"(a[i][2]), "=r"(a[i][3])
                             : "r"(ad));
            }
#pragma unroll
            for (int jj = 0; jj < 4; jj++) {
                int krow = k0 + (lane & 7) + ((lane >> 3) & 1) * 8;
                int ncol = warp_n * 64 + jj * 16 + (lane >> 4) * 8;
                uint32_t ad = bB + (uint32_t)(krow * G2_BROWB + ncol * 2);
                asm volatile("ldmatrix.sync.aligned.m8n8.x4.trans.shared.b16 {%0,%1,%2,%3}, [%4];"
                             : "=r"(b[jj * 2][0]), "=r"(b[jj * 2][1]),
                               "=r"(b[jj * 2 + 1][0]), "=r"(b[jj * 2 + 1][1])
                             : "r"(ad));
            }
#pragma unroll
            for (int i = 0; i < 4; i++)
#pragma unroll
                for (int j = 0; j < 8; j++) {
                    asm volatile(
                        "mma.sync.aligned.m16n8k16.row.col.f16.f16.f16.f16 "
                        "{%0,%1}, {%2,%3,%4,%5}, {%6,%7}, {%0,%1};"
                        : "+r"(c[i][j][0]), "+r"(c[i][j][1])
                        : "r"(a[i][0]), "r"(a[i][1]), "r"(a[i][2]), "r"(a[i][3]),
                          "r"(b[j][0]), "r"(b[j][1]));
                }
        }
    };

    issue(0);
    issue(1);
    issue(2);

    for (int kt = 0; kt < G2_KT; kt++) {
        if (kt < G2_KT - 2)      { asm volatile("cp.async.wait_group 2;\n"); }
        else if (kt < G2_KT - 1) { asm volatile("cp.async.wait_group 1;\n"); }
        else                     { asm volatile("cp.async.wait_group 0;\n"); }
        __syncthreads();
        if (kt + 3 < G2_KT) issue(kt + 3);
        compute(kt);
    }

    // -------- epilogue --------
    if (tid < G2_BM) srow[tid] = 0.f;
    __syncthreads();

    float rs[4][2];
#pragma unroll
    for (int i = 0; i < 4; i++) { rs[i][0] = 0.f; rs[i][1] = 0.f; }

#pragma unroll
    for (int j = 0; j < 8; j++) {
        int col = nBase + warp_n * 64 + j * 8 + (lane & 3) * 2;
        float b0 = bias[col], b1 = bias[col + 1];
#pragma unroll
        for (int i = 0; i < 4; i++) {
            int row = mBase + warp_m * 64 + i * 16 + (lane >> 2);
            float2 f0 = __half22float2(*reinterpret_cast<__half2*>(&c[i][j][0]));
            float2 f1 = __half22float2(*reinterpret_cast<__half2*>(&c[i][j][1]));
            float v00 = f0.x + b0, v01 = f0.y + b1;
            float v10 = f1.x + b0, v11 = f1.y + b1;
            *reinterpret_cast<__half2*>(&g_logits[(size_t)row * Vk + col]) =
                __floats2half2_rn(v00, v01);
            *reinterpret_cast<__half2*>(&g_logits[(size_t)(row + 8) * Vk + col]) =
                __floats2half2_rn(v10, v11);
            rs[i][0] += __expf(v00) + __expf(v01);
            rs[i][1] += __expf(v10) + __expf(v11);
        }
    }
#pragma unroll
    for (int i = 0; i < 4; i++)
#pragma unroll
        for (int h = 0; h < 2; h++) {
            float v = rs[i][h];
            v += __shfl_xor_sync(0xffffffffu, v, 1);
            v += __shfl_xor_sync(0xffffffffu, v, 2);
            if ((lane & 3) == 0)
                atomicAdd(&srow[warp_m * 64 + i * 16 + (lane >> 2) + h * 8], v);
        }
    __syncthreads();
    if (tid < G2_BM) atomicAdd(&g_sumexp[mBase + tid], srow[tid]);
}

// ---------------------------------------------------------------------------
// w[l,e] = exp(log_coef) / sumexp
// ---------------------------------------------------------------------------
__global__ void prep_w_kernel() {
    int m = blockIdx.x * blockDim.x + threadIdx.x;
    if (m < M2k) g_w[m] = __expf(g_logcoef[m]) / g_sumexp[m];
}

// ---------------------------------------------------------------------------
// out[l,v] = log( sum_e w[l,e] * exp(logit[l,e,v]) )
// ---------------------------------------------------------------------------
__global__ void combine_kernel(float* __restrict__ out) {
    int v = (blockIdx.x * blockDim.x + threadIdx.x) * 2;
    int l = blockIdx.y;
    const __half* lp = g_logits + (size_t)l * Ek * Vk + v;
    const float*  wp = g_w + l * Ek;
    float s0 = 0.f, s1 = 0.f;
#pragma unroll
    for (int e = 0; e < Ek; e++) {
        __half2 h2 = *reinterpret_cast<const __half2*>(lp + (size_t)e * Vk);
        float2 f2 = __half22float2(h2);
        float we = wp[e];
        s0 += we * __expf(f2.x);
        s1 += we * __expf(f2.y);
    }
    float2* o2 = reinterpret_cast<float2*>(out + (size_t)l * Vk + v);
    *o2 = make_float2(__logf(s0), __logf(s1));
}

// ---------------------------------------------------------------------------
// Entry point (graph-capturable: kernel launches only)
// ---------------------------------------------------------------------------
extern "C" void kernel_launch(void* const* d_in, const int* in_sizes, int n_in,
                              void* d_out, int out_size) {
    const float* H  = (const float*)d_in[0];
    const float* Wp = (const float*)d_in[1];
    const float* bp = (const float*)d_in[2];
    const float* Wl = (const float*)d_in[3];
    const float* bl = (const float*)d_in[4];
    const float* Wd = (const float*)d_in[5];
    const float* bd = (const float*)d_in[6];
    float* out = (float*)d_out;

    static bool attr_set = false;
    if (!attr_set) {
        cudaFuncSetAttribute(gemm2_kernel,
                             cudaFuncAttributeMaxDynamicSharedMemorySize, G2_DSMEM);
        attr_set = true;
    }

    conv_kernel<<<2048, 256>>>(H, Wl, Wd);
    prior_kernel<<<128, 256>>>(H, Wp, bp);
    gemm1_kernel<<<dim3(N1k / BN1, Lk / BM1), 256>>>(bl);                 // (16, 8)
    gemm2_kernel<<<dim3(Vk / G2_BN, M2k / G2_BM), 256, G2_DSMEM>>>(bd);   // (125, 32)
    prep_w_kernel<<<(M2k + 255) / 256, 256>>>();
    combine_kernel<<<dim3(125, Lk), 128>>>(out);                          // (125, 1024)
}

// round 7
// speedup vs baseline: 1.1785x; 1.0289x over previous
#include <cuda_runtime.h>
#include <cuda_bf16.h>
#include <cuda_fp16.h>
#include <cstdint>

// Problem constants
#define Dk   512
#define Ek   4
#define Vk   32000
#define Lk   1024
#define M2k  (Lk * Ek)     // 4096 rows for the big GEMM
#define N1k  (Ek * Dk)     // 2048 latent width

// ---------------------------------------------------------------------------
// Device scratch (allocation-free: static __device__ arrays)
// ---------------------------------------------------------------------------
__device__ __nv_bfloat16 g_Hbf[Lk * Dk];                 // hidden bf16 [1024][512]
__device__ __nv_bfloat16 g_Wlat[Dk * N1k];               // W_latent bf16 [512][2048]
__device__ __half        g_WdecH[Dk * Vk];               // W_dec fp16 [512][32000]
__device__ __half        g_latent[M2k * Dk];             // tanh latent fp16 [4096][512]
__device__ __half        g_logits[(size_t)M2k * Vk];     // 262 MB logits scratch (fp16)
__device__ float         g_logcoef[M2k];                 // log softmax of priors
__device__ float         g_sumexp[M2k];                  // per-(l,e) sum of exp(logit)
__device__ float         g_w[M2k];                       // exp(logcoef)/sumexp

__device__ __forceinline__ uint32_t smem_u32(const void* p) {
    return (uint32_t)__cvta_generic_to_shared(p);
}
__device__ __forceinline__ void cpasync16(uint32_t sp, const void* gp) {
    asm volatile("cp.async.cg.shared.global [%0], [%1], 16;\n" :: "r"(sp), "l"(gp));
}

// ---------------------------------------------------------------------------
// fp32 -> bf16 / fp16 conversions
// ---------------------------------------------------------------------------
__global__ void conv_kernel(const float* __restrict__ H,
                            const float* __restrict__ Wl,
                            const float* __restrict__ Wd) {
    int stride = gridDim.x * blockDim.x;
    int tid = blockIdx.x * blockDim.x + threadIdx.x;
    for (int j = tid; j < Lk * Dk; j += stride)  g_Hbf[j]  = __float2bfloat16(H[j]);
    for (int j = tid; j < Dk * N1k; j += stride) g_Wlat[j] = __float2bfloat16(Wl[j]);
    for (int j = tid; j < Dk * Vk; j += stride)  g_WdecH[j] = __float2half(Wd[j]);
}

// ---------------------------------------------------------------------------
// Prior: one warp per token, 4 dots + log_softmax. Also zeroes g_sumexp.
// ---------------------------------------------------------------------------
__global__ void prior_kernel(const float* __restrict__ H,
                             const float* __restrict__ Wp,
                             const float* __restrict__ bp) {
    int gtid = blockIdx.x * blockDim.x + threadIdx.x;
    if (gtid < M2k) g_sumexp[gtid] = 0.f;
    int w = gtid >> 5, lane = gtid & 31;
    if (w >= Lk) return;
    float a0 = 0.f, a1 = 0.f, a2 = 0.f, a3 = 0.f;
    const float* h = H + w * Dk;
    for (int d = lane; d < Dk; d += 32) {
        float hv = h[d];
        const float* wr = Wp + d * Ek;
        a0 += hv * wr[0]; a1 += hv * wr[1]; a2 += hv * wr[2]; a3 += hv * wr[3];
    }
#pragma unroll
    for (int o = 16; o; o >>= 1) {
        a0 += __shfl_xor_sync(0xffffffffu, a0, o);
        a1 += __shfl_xor_sync(0xffffffffu, a1, o);
        a2 += __shfl_xor_sync(0xffffffffu, a2, o);
        a3 += __shfl_xor_sync(0xffffffffu, a3, o);
    }
    if (lane == 0) {
        float x0 = a0 + bp[0], x1 = a1 + bp[1], x2 = a2 + bp[2], x3 = a3 + bp[3];
        float mx = fmaxf(fmaxf(x0, x1), fmaxf(x2, x3));
        float s = __expf(x0 - mx) + __expf(x1 - mx) + __expf(x2 - mx) + __expf(x3 - mx);
        float lse = mx + __logf(s);
        g_logcoef[w * Ek + 0] = x0 - lse;  g_logcoef[w * Ek + 1] = x1 - lse;
        g_logcoef[w * Ek + 2] = x2 - lse;  g_logcoef[w * Ek + 3] = x3 - lse;
    }
}

// ---------------------------------------------------------------------------
// GEMM1 (latent): bf16 in, fp32 accum, 128x128x32 tiles; out -> fp16 latent
// ---------------------------------------------------------------------------
#define BM1 128
#define BN1 128
#define BK1 32
#define KT1 (Dk / BK1)
#define PADA 40
#define PADB 136

__global__ __launch_bounds__(256, 2) void gemm1_kernel(const float* __restrict__ bias) {
    const int N = N1k;
    const __nv_bfloat16* __restrict__ A  = g_Hbf;
    const __nv_bfloat16* __restrict__ Bm = g_Wlat;

    __shared__ __align__(16) __nv_bfloat16 As[2][BM1][PADA];
    __shared__ __align__(16) __nv_bfloat16 Bs[2][BK1][PADB];

    const int tid = threadIdx.x, lane = tid & 31, wid = tid >> 5;
    const int warp_m = wid >> 2, warp_n = wid & 3;
    const int mBase = blockIdx.y * BM1, nBase = blockIdx.x * BN1;

    float c[4][4][4];
#pragma unroll
    for (int i = 0; i < 4; i++)
#pragma unroll
        for (int j = 0; j < 4; j++)
#pragma unroll
            for (int r = 0; r < 4; r++) c[i][j][r] = 0.f;

    auto issue = [&](int kt, int buf) {
#pragma unroll
        for (int s = 0; s < 2; s++) {
            int chunk = tid + s * 256;
            int arow = chunk >> 2, ac4 = chunk & 3;
            cpasync16(smem_u32(&As[buf][arow][ac4 * 8]),
                      A + (size_t)(mBase + arow) * Dk + kt * BK1 + ac4 * 8);
        }
#pragma unroll
        for (int s = 0; s < 2; s++) {
            int chunk = tid + s * 256;
            int brow = chunk >> 4, bc4 = chunk & 15;
            cpasync16(smem_u32(&Bs[buf][brow][bc4 * 8]),
                      Bm + (size_t)(kt * BK1 + brow) * N + nBase + bc4 * 8);
        }
    };

    auto compute = [&](int buf) {
#pragma unroll
        for (int ks = 0; ks < 2; ks++) {
            const int k0 = ks * 16;
            uint32_t a[4][4], b[4][2];
#pragma unroll
            for (int i = 0; i < 4; i++) {
                int row = warp_m * 64 + i * 16 + (lane & 7) + ((lane >> 3) & 1) * 8;
                int col = k0 + (lane >> 4) * 8;
                uint32_t ad = smem_u32(&As[buf][row][col]);
                asm volatile("ldmatrix.sync.aligned.m8n8.x4.shared.b16 {%0,%1,%2,%3}, [%4];"
                             : "=r"(a[i][0]), "=r"(a[i][1]), "=r"(a[i][2]), "=r"(a[i][3])
                             : "r"(ad));
            }
#pragma unroll
            for (int jj = 0; jj < 2; jj++) {
                int krow = k0 + (lane & 7) + ((lane >> 3) & 1) * 8;
                int ncol = warp_n * 32 + jj * 16 + (lane >> 4) * 8;
                uint32_t ad = smem_u32(&Bs[buf][krow][ncol]);
                asm volatile("ldmatrix.sync.aligned.m8n8.x4.trans.shared.b16 {%0,%1,%2,%3}, [%4];"
                             : "=r"(b[jj * 2][0]), "=r"(b[jj * 2][1]),
                               "=r"(b[jj * 2 + 1][0]), "=r"(b[jj * 2 + 1][1])
                             : "r"(ad));
            }
#pragma unroll
            for (int i = 0; i < 4; i++)
#pragma unroll
                for (int j = 0; j < 4; j++) {
                    asm volatile(
                        "mma.sync.aligned.m16n8k16.row.col.f32.bf16.bf16.f32 "
                        "{%0,%1,%2,%3}, {%4,%5,%6,%7}, {%8,%9}, {%0,%1,%2,%3};"
                        : "+f"(c[i][j][0]), "+f"(c[i][j][1]), "+f"(c[i][j][2]), "+f"(c[i][j][3])
                        : "r"(a[i][0]), "r"(a[i][1]), "r"(a[i][2]), "r"(a[i][3]),
                          "r"(b[j][0]), "r"(b[j][1]));
                }
        }
    };

    issue(0, 0);
    asm volatile("cp.async.commit_group;\n");
    issue(1, 1);
    asm volatile("cp.async.commit_group;\n");

    for (int kt = 0; kt < KT1; kt++) {
        if (kt < KT1 - 1) { asm volatile("cp.async.wait_group 1;\n"); }
        else              { asm volatile("cp.async.wait_group 0;\n"); }
        __syncthreads();
        compute(kt & 1);
        if (kt + 2 < KT1) {
            __syncthreads();
            issue(kt + 2, kt & 1);
            asm volatile("cp.async.commit_group;\n");
        }
    }

#pragma unroll
    for (int j = 0; j < 4; j++) {
        int col = nBase + warp_n * 32 + j * 8 + (lane & 3) * 2;
        float b0 = bias[col], b1 = bias[col + 1];
#pragma unroll
        for (int i = 0; i < 4; i++) {
            int row = mBase + warp_m * 64 + i * 16 + (lane >> 2);
            __half2 p0 = __floats2half2_rn(tanhf(c[i][j][0] + b0), tanhf(c[i][j][1] + b1));
            __half2 p1 = __floats2half2_rn(tanhf(c[i][j][2] + b0), tanhf(c[i][j][3] + b1));
            *reinterpret_cast<__half2*>(&g_latent[(size_t)row * N + col]) = p0;
            *reinterpret_cast<__half2*>(&g_latent[(size_t)(row + 8) * N + col]) = p1;
        }
    }
}

// ---------------------------------------------------------------------------
// GEMM2 (decoder): fp16 in/accum, CTA 128x256, warp tile 64x64.
// BK=64, 2-stage pipeline (8 barriers instead of 16), 2 CTAs/SM.
// Per-chunk: load(kt+1) issued before compute(kt) -> overlap.
// ---------------------------------------------------------------------------
#define G2_BM 128
#define G2_BN 256
#define G2_BK 64
#define G2_KT (Dk / G2_BK)              // 8
#define G2_AROWB 144                    // (64+8) fp16 = 144B, 36 banks = 4 mod 32
#define G2_BROWB 528                    // (256+8) fp16 = 528B, 132 banks = 4 mod 32
#define G2_ABYTES (G2_BM * G2_AROWB)    // 18432
#define G2_BBYTES (G2_BK * G2_BROWB)    // 33792
#define G2_STG    (G2_ABYTES + G2_BBYTES)   // 52224
#define G2_NSTG   2
#define G2_DSMEM  (G2_NSTG * G2_STG)        // 104448

__global__ __launch_bounds__(256, 2) void gemm2_kernel(const float* __restrict__ bias) {
    extern __shared__ char dsm[];
    __shared__ float srow[G2_BM];

    const int tid  = threadIdx.x;
    const int lane = tid & 31;
    const int wid  = tid >> 5;
    const int warp_m = wid >> 2;       // 0..1
    const int warp_n = wid & 3;        // 0..3
    const int mBase = blockIdx.y * G2_BM;
    const int nBase = blockIdx.x * G2_BN;

    const uint32_t s0 = smem_u32(dsm);
    const __half* __restrict__ A  = g_latent;
    const __half* __restrict__ Bm = g_WdecH;

    uint32_t c[4][8][2];
#pragma unroll
    for (int i = 0; i < 4; i++)
#pragma unroll
        for (int j = 0; j < 8; j++) { c[i][j][0] = 0u; c[i][j][1] = 0u; }

    auto issue = [&](int kt) {
        const uint32_t aB = s0 + (uint32_t)(kt & 1) * G2_STG;
        const uint32_t bB = aB + G2_ABYTES;
        const int kOff = kt * G2_BK;
#pragma unroll
        for (int s = 0; s < 4; s++) {              // A: 128 rows x 8 chunks = 1024
            int ch = tid + s * 256;
            int row = ch >> 3, cc = ch & 7;
            cpasync16(aB + (uint32_t)(row * G2_AROWB + cc * 16),
                      A + (size_t)(mBase + row) * Dk + kOff + cc * 8);
        }
#pragma unroll
        for (int s = 0; s < 8; s++) {              // B: 64 rows x 32 chunks = 2048
            int ch = tid + s * 256;
            int row = ch >> 5, cc = ch & 31;
            cpasync16(bB + (uint32_t)(row * G2_BROWB + cc * 16),
                      Bm + (size_t)(kOff + row) * Vk + nBase + cc * 8);
        }
        asm volatile("cp.async.commit_group;\n");
    };

    auto compute = [&](int kt) {
        const uint32_t aB = s0 + (uint32_t)(kt & 1) * G2_STG;
        const uint32_t bB = aB + G2_ABYTES;
#pragma unroll
        for (int ks = 0; ks < 4; ks++) {
            const int k0 = ks * 16;
            uint32_t a[4][4], b[8][2];
#pragma unroll
            for (int i = 0; i < 4; i++) {
                int row = warp_m * 64 + i * 16 + (lane & 7) + ((lane >> 3) & 1) * 8;
                int col = k0 + (lane >> 4) * 8;
                uint32_t ad = aB + (uint32_t)(row * G2_AROWB + col * 2);
                asm volatile("ldmatrix.sync.aligned.m8n8.x4.shared.b16 {%0,%1,%2,%3}, [%4];"
                             : "=r"(a[i][0]), "=r"(a[i][1]), "=r"(a[i][2]), "=r"(a[i][3])
                             : "r"(ad));
            }
#pragma unroll
            for (int jj = 0; jj < 4; jj++) {
                int krow = k0 + (lane & 7) + ((lane >> 3) & 1) * 8;
                int ncol = warp_n * 64 + jj * 16 + (lane >> 4) * 8;
                uint32_t ad = bB + (uint32_t)(krow * G2_BROWB + ncol * 2);
                asm volatile("ldmatrix.sync.aligned.m8n8.x4.trans.shared.b16 {%0,%1,%2,%3}, [%4];"
                             : "=r"(b[jj * 2][0]), "=r"(b[jj * 2][1]),
                               "=r"(b[jj * 2 + 1][0]), "=r"(b[jj * 2 + 1][1])
                             : "r"(ad));
            }
#pragma unroll
            for (int i = 0; i < 4; i++)
#pragma unroll
                for (int j = 0; j < 8; j++) {
                    asm volatile(
                        "mma.sync.aligned.m16n8k16.row.col.f16.f16.f16.f16 "
                        "{%0,%1}, {%2,%3,%4,%5}, {%6,%7}, {%0,%1};"
                        : "+r"(c[i][j][0]), "+r"(c[i][j][1])
                        : "r"(a[i][0]), "r"(a[i][1]), "r"(a[i][2]), "r"(a[i][3]),
                          "r"(b[j][0]), "r"(b[j][1]));
                }
        }
    };

    issue(0);

    for (int kt = 0; kt < G2_KT; kt++) {
        asm volatile("cp.async.wait_group 0;\n");   // chunk kt resident
        __syncthreads();                             // all warps done with buffer kt+1's slot
        if (kt + 1 < G2_KT) issue(kt + 1);           // overlap next load with compute
        compute(kt);
    }

    // -------- epilogue --------
    if (tid < G2_BM) srow[tid] = 0.f;
    __syncthreads();

    float rs[4][2];
#pragma unroll
    for (int i = 0; i < 4; i++) { rs[i][0] = 0.f; rs[i][1] = 0.f; }

#pragma unroll
    for (int j = 0; j < 8; j++) {
        int col = nBase + warp_n * 64 + j * 8 + (lane & 3) * 2;
        float b0 = bias[col], b1 = bias[col + 1];
#pragma unroll
        for (int i = 0; i < 4; i++) {
            int row = mBase + warp_m * 64 + i * 16 + (lane >> 2);
            float2 f0 = __half22float2(*reinterpret_cast<__half2*>(&c[i][j][0]));
            float2 f1 = __half22float2(*reinterpret_cast<__half2*>(&c[i][j][1]));
            float v00 = f0.x + b0, v01 = f0.y + b1;
            float v10 = f1.x + b0, v11 = f1.y + b1;
            *reinterpret_cast<__half2*>(&g_logits[(size_t)row * Vk + col]) =
                __floats2half2_rn(v00, v01);
            *reinterpret_cast<__half2*>(&g_logits[(size_t)(row + 8) * Vk + col]) =
                __floats2half2_rn(v10, v11);
            rs[i][0] += __expf(v00) + __expf(v01);
            rs[i][1] += __expf(v10) + __expf(v11);
        }
    }
#pragma unroll
    for (int i = 0; i < 4; i++)
#pragma unroll
        for (int h = 0; h < 2; h++) {
            float v = rs[i][h];
            v += __shfl_xor_sync(0xffffffffu, v, 1);
            v += __shfl_xor_sync(0xffffffffu, v, 2);
            if ((lane & 3) == 0)
                atomicAdd(&srow[warp_m * 64 + i * 16 + (lane >> 2) + h * 8], v);
        }
    __syncthreads();
    if (tid < G2_BM) atomicAdd(&g_sumexp[mBase + tid], srow[tid]);
}

// ---------------------------------------------------------------------------
// w[l,e] = exp(log_coef) / sumexp
// ---------------------------------------------------------------------------
__global__ void prep_w_kernel() {
    int m = blockIdx.x * blockDim.x + threadIdx.x;
    if (m < M2k) g_w[m] = __expf(g_logcoef[m]) / g_sumexp[m];
}

// ---------------------------------------------------------------------------
// out[l,v] = log( sum_e w[l,e] * exp(logit[l,e,v]) )
// ---------------------------------------------------------------------------
__global__ void combine_kernel(float* __restrict__ out) {
    int v = (blockIdx.x * blockDim.x + threadIdx.x) * 2;
    int l = blockIdx.y;
    const __half* lp = g_logits + (size_t)l * Ek * Vk + v;
    const float*  wp = g_w + l * Ek;
    float s0 = 0.f, s1 = 0.f;
#pragma unroll
    for (int e = 0; e < Ek; e++) {
        __half2 h2 = *reinterpret_cast<const __half2*>(lp + (size_t)e * Vk);
        float2 f2 = __half22float2(h2);
        float we = wp[e];
        s0 += we * __expf(f2.x);
        s1 += we * __expf(f2.y);
    }
    float2* o2 = reinterpret_cast<float2*>(out + (size_t)l * Vk + v);
    *o2 = make_float2(__logf(s0), __logf(s1));
}

// ---------------------------------------------------------------------------
// Entry point (graph-capturable: kernel launches only)
// ---------------------------------------------------------------------------
extern "C" void kernel_launch(void* const* d_in, const int* in_sizes, int n_in,
                              void* d_out, int out_size) {
    const float* H  = (const float*)d_in[0];
    const float* Wp = (const float*)d_in[1];
    const float* bp = (const float*)d_in[2];
    const float* Wl = (const float*)d_in[3];
    const float* bl = (const float*)d_in[4];
    const float* Wd = (const float*)d_in[5];
    const float* bd = (const float*)d_in[6];
    float* out = (float*)d_out;

    static bool attr_set = false;
    if (!attr_set) {
        cudaFuncSetAttribute(gemm2_kernel,
                             cudaFuncAttributeMaxDynamicSharedMemorySize, G2_DSMEM);
        attr_set = true;
    }

    conv_kernel<<<2048, 256>>>(H, Wl, Wd);
    prior_kernel<<<128, 256>>>(H, Wp, bp);
    gemm1_kernel<<<dim3(N1k / BN1, Lk / BM1), 256>>>(bl);                 // (16, 8)
    gemm2_kernel<<<dim3(Vk / G2_BN, M2k / G2_BM), 256, G2_DSMEM>>>(bd);   // (125, 32)
    prep_w_kernel<<<(M2k + 255) / 256, 256>>>();
    combine_kernel<<<dim3(125, Lk), 128>>>(out);                          // (125, 1024)
}